// round 1
// baseline (speedup 1.0000x reference)
#include <cuda_runtime.h>
#include <float.h>
#include <math.h>

// Problem constants
#define NPTS 12288
#define DIM 64
#define KNN 16
#define EPS 1e-5f
#define DIAG_BIAS 1e6f

// Tiling
#define NSEG 6
#define SEG (NPTS / NSEG)        // 2048
#define TILE_J 64
#define RPB 256                  // rows per block == threads per block
#define NROWBLK (NPTS / RPB)     // 48

// Scratch (no allocations allowed -> device globals)
__device__ float g_sq[NPTS];
__device__ float g_colsum[DIM];
__device__ float g_sigma_inv;                 // 1 / (sigma2 + EPS)
__device__ float g_vals[NPTS * NSEG * KNN];
__device__ int   g_idx [NPTS * NSEG * KNN];

// ---------------------------------------------------------------------------
// Kernel A1: per-row squared norm
// ---------------------------------------------------------------------------
__global__ void sq_kernel(const float* __restrict__ coords) {
    int row = blockIdx.x * RPB + threadIdx.x;
    const float4* p = (const float4*)(coords + (size_t)row * DIM);
    float s = 0.f;
#pragma unroll
    for (int t = 0; t < DIM / 4; ++t) {
        float4 v = p[t];
        s += v.x * v.x + v.y * v.y + v.z * v.z + v.w * v.w;
    }
    g_sq[row] = s;
}

// ---------------------------------------------------------------------------
// Kernel A1b: column sums (one block per dim), deterministic tree reduce
// ---------------------------------------------------------------------------
__global__ void colsum_kernel(const float* __restrict__ coords) {
    __shared__ float red[256];
    int d = blockIdx.x;
    float s = 0.f;
    for (int r = threadIdx.x; r < NPTS; r += 256)
        s += coords[(size_t)r * DIM + d];
    red[threadIdx.x] = s;
    __syncthreads();
    for (int off = 128; off > 0; off >>= 1) {
        if (threadIdx.x < off) red[threadIdx.x] += red[threadIdx.x + off];
        __syncthreads();
    }
    if (threadIdx.x == 0) g_colsum[d] = red[0];
}

// ---------------------------------------------------------------------------
// Kernel A2: analytic sigma2 (single block, deterministic)
//   sum_ij dist2 = 2N*sum(sq) - 2*||colsum||^2 + N^2*EPS + N*DIAG_BIAS
// ---------------------------------------------------------------------------
__global__ void sigma_kernel() {
    __shared__ double red[256];
    double s = 0.0;
    for (int r = threadIdx.x; r < NPTS; r += 256)
        s += (double)g_sq[r];
    red[threadIdx.x] = s;
    __syncthreads();
    for (int off = 128; off > 0; off >>= 1) {
        if (threadIdx.x < off) red[threadIdx.x] += red[threadIdx.x + off];
        __syncthreads();
    }
    if (threadIdx.x == 0) {
        double sumsq = red[0];
        double nrm2 = 0.0;
        for (int d = 0; d < DIM; ++d) {
            double c = (double)g_colsum[d];
            nrm2 += c * c;
        }
        const double Nd = (double)NPTS;
        double total = 2.0 * Nd * sumsq - 2.0 * nrm2
                     + Nd * Nd * (double)EPS + Nd * (double)DIAG_BIAS;
        double sigma2 = total / (Nd * Nd);
        g_sigma_inv = (float)(1.0 / (sigma2 + (double)EPS));
    }
}

// ---------------------------------------------------------------------------
// Sorted insert: vals kept ascending, vals[KNN-1] is the current threshold.
// Fully unrolled -> static register indices, no local-memory spill by design.
// ---------------------------------------------------------------------------
__device__ __forceinline__ void topk_insert(float (&vals)[KNN], int (&idx)[KNN],
                                            float v, int id) {
#pragma unroll
    for (int t = 0; t < KNN; ++t) {
        if (v < vals[t]) {
            float tv = vals[t]; vals[t] = v; v = tv;
            int   ti = idx[t];  idx[t]  = id; id = ti;
        }
    }
}

// ---------------------------------------------------------------------------
// Kernel B: per-(row, segment) top-16 of squared distances.
// One thread = one row. x_i in registers, j-tiles staged in smem (broadcast).
// ---------------------------------------------------------------------------
__global__ void __launch_bounds__(RPB)
knn_kernel(const float* __restrict__ coords) {
    const int row = blockIdx.x * RPB + threadIdx.x;
    const int seg = blockIdx.y;
    const int j0  = seg * SEG;

    // Load x_i into registers (64 floats)
    float4 xi[DIM / 4];
    {
        const float4* p = (const float4*)(coords + (size_t)row * DIM);
#pragma unroll
        for (int t = 0; t < DIM / 4; ++t) xi[t] = p[t];
    }
    const float sqi = g_sq[row];

    float vals[KNN];
    int   idx[KNN];
#pragma unroll
    for (int t = 0; t < KNN; ++t) { vals[t] = FLT_MAX; idx[t] = 0; }

    __shared__ float sj[TILE_J * DIM];   // 16 KB
    __shared__ float ssq[TILE_J];

    for (int jt = 0; jt < SEG; jt += TILE_J) {
        const int base = j0 + jt;
        __syncthreads();
        // Stage 64 x 64 fp32 tile: 1024 float4, 4 per thread, coalesced.
        {
            const float4* src = (const float4*)(coords + (size_t)base * DIM);
            float4* dst = (float4*)sj;
#pragma unroll
            for (int t = 0; t < 4; ++t) {
                int e = threadIdx.x + t * RPB;
                dst[e] = src[e];
            }
            if (threadIdx.x < TILE_J) ssq[threadIdx.x] = g_sq[base + threadIdx.x];
        }
        __syncthreads();

#pragma unroll 1
        for (int jj = 0; jj < TILE_J; jj += 2) {
            const float4* b0 = (const float4*)(sj + (jj + 0) * DIM);
            const float4* b1 = (const float4*)(sj + (jj + 1) * DIM);
            float a0 = 0.f, a1 = 0.f, a2 = 0.f, a3 = 0.f;
#pragma unroll
            for (int t = 0; t < DIM / 4; t += 2) {
                float4 u0 = b0[t], u1 = b0[t + 1];
                float4 w0 = b1[t], w1 = b1[t + 1];
                a0 += xi[t].x * u0.x + xi[t].y * u0.y + xi[t].z * u0.z + xi[t].w * u0.w;
                a1 += xi[t + 1].x * u1.x + xi[t + 1].y * u1.y + xi[t + 1].z * u1.z + xi[t + 1].w * u1.w;
                a2 += xi[t].x * w0.x + xi[t].y * w0.y + xi[t].z * w0.z + xi[t].w * w0.w;
                a3 += xi[t + 1].x * w1.x + xi[t + 1].y * w1.y + xi[t + 1].z * w1.z + xi[t + 1].w * w1.w;
            }
            const int jg0 = base + jj, jg1 = base + jj + 1;
            float d0 = sqi + ssq[jj + 0] - 2.f * (a0 + a1) + EPS;
            float d1 = sqi + ssq[jj + 1] - 2.f * (a2 + a3) + EPS;
            if (jg0 == row) d0 += DIAG_BIAS;
            if (jg1 == row) d1 += DIAG_BIAS;
            if (d0 < vals[KNN - 1]) topk_insert(vals, idx, d0, jg0);
            if (d1 < vals[KNN - 1]) topk_insert(vals, idx, d1, jg1);
        }
    }

    // Emit per-segment candidates
    const size_t o = ((size_t)row * NSEG + seg) * KNN;
#pragma unroll
    for (int t = 0; t < KNN; ++t) {
        g_vals[o + t] = vals[t];
        g_idx [o + t] = idx[t];
    }
}

// ---------------------------------------------------------------------------
// Kernel C: merge NSEG candidate lists per row, compute Laplacian.
// ---------------------------------------------------------------------------
__global__ void merge_lap_kernel(const float* __restrict__ potential,
                                 float* __restrict__ out) {
    const int row = blockIdx.x * RPB + threadIdx.x;

    float vals[KNN];
    int   idx[KNN];
#pragma unroll
    for (int t = 0; t < KNN; ++t) { vals[t] = FLT_MAX; idx[t] = 0; }

    const size_t base = (size_t)row * NSEG * KNN;
    // Segments in ascending order, values within a segment ascending:
    // strict '<' insert preserves lowest-index-first on ties (matches top_k).
    for (int s = 0; s < NSEG; ++s) {
#pragma unroll
        for (int kk = 0; kk < KNN; ++kk) {
            float c = g_vals[base + s * KNN + kk];
            if (c < vals[KNN - 1]) topk_insert(vals, idx, c, g_idx[base + s * KNN + kk]);
        }
    }

    const float inv = g_sigma_inv;
    const float vi  = potential[row];
    float lap = 0.f;
#pragma unroll
    for (int t = 0; t < KNN; ++t) {
        float w = expf(-vals[t] * inv);        // exp(knn_val / (sigma2+eps)), knn_val = -dist2
        lap += w * (potential[idx[t]] - vi);
    }
    out[row] = lap;
}

// ---------------------------------------------------------------------------
extern "C" void kernel_launch(void* const* d_in, const int* in_sizes, int n_in,
                              void* d_out, int out_size) {
    const float* coords    = (const float*)d_in[0];
    const float* potential = (const float*)d_in[1];
    // d_in[2] is k (== 16), compile-time constant here
    float* out = (float*)d_out;

    sq_kernel<<<NROWBLK, RPB>>>(coords);
    colsum_kernel<<<DIM, 256>>>(coords);
    sigma_kernel<<<1, 256>>>();

    dim3 grid(NROWBLK, NSEG);
    knn_kernel<<<grid, RPB>>>(coords);

    merge_lap_kernel<<<NROWBLK, RPB>>>(potential, out);
}